// round 14
// baseline (speedup 1.0000x reference)
#include <cuda_runtime.h>
#include <cuda_bf16.h>
#include <cuda_fp16.h>
#include <cstdint>

// Flash-attention, no-online-softmax (scores bounded -> fixed exp base).
// GEMM1 = fp16 2-term (Q hi/lo vs fp16 K, scale folded into K), ldmatrix B-frags.
// GEMM2 = fp16 single-term. l = sum(p) via HADD2 tree on masked P words
// (fp32 across tiles) -- no more tensor-core ones-column (saves 4 HMMA/tile).
// Tile body split into two self-contained phases (GEMM1 half -> softmax
// chunk-pair -> GEMM2 k-half) to halve live registers -> 5 CTAs/SM.
// B=4,H=8,L=2048,E=32. CTA: 128 thr (4 warps), TQ=64 (16 rows/warp), TK=64.

constexpr int Bdim = 4, Hdim = 8, Ldim = 2048, Edim = 32;
constexpr int TQ = 64, TK = 64, NT = Ldim / TK;
constexpr float SCALE_LOG2 = 0.25507312986795477f;  // log2(e)/TEMPERATURE
constexpr int KST = 40;   // k tile row stride (half): ldmatrix conflict-free
constexpr int VST = 72;   // vT tile row stride (half): ldmatrix conflict-free
constexpr int VROWS = 32; // data rows only (no ones column)

// prep grid split
constexpr int PREP_KBLK = (Bdim * Hdim * Ldim * Edim / 4) / 256;  // 2048
constexpr int PREP_VBLK = (Bdim * Hdim) * (Ldim / 64);            // 1024
constexpr int PREP_MBLK = Bdim * Ldim;                            // 8192

// ---- preprocessed scratch ----
__device__ __half   g_kh[Bdim * Hdim * Ldim * Edim];      // scaled fp16 K
__device__ __half   g_vt[Bdim * Hdim * Edim * Ldim];      // [b,h,e,key] fp16
__device__ uint8_t  g_mpack[(long)Bdim * Ldim * 32 * 8];  // [b*L+i][j8][t*2+ab]

__device__ __forceinline__ uint32_t h2ex2(uint32_t x) {
    uint32_t y;
    asm("ex2.approx.f16x2 %0, %1;" : "=r"(y) : "r"(x));
    return y;
}

__device__ __forceinline__ void mma_f16(float c[4], const uint32_t a[4],
                                        uint32_t b0, uint32_t b1) {
    asm volatile(
        "mma.sync.aligned.m16n8k16.row.col.f32.f16.f16.f32 "
        "{%0,%1,%2,%3},{%4,%5,%6,%7},{%8,%9},{%0,%1,%2,%3};"
        : "+f"(c[0]), "+f"(c[1]), "+f"(c[2]), "+f"(c[3])
        : "r"(a[0]), "r"(a[1]), "r"(a[2]), "r"(a[3]), "r"(b0), "r"(b1));
}

__device__ __forceinline__ void ldsm4(uint32_t& a, uint32_t& b, uint32_t& c,
                                      uint32_t& d, uint32_t addr) {
    asm volatile(
        "ldmatrix.sync.aligned.m8n8.x4.shared.b16 {%0,%1,%2,%3}, [%4];"
        : "=r"(a), "=r"(b), "=r"(c), "=r"(d) : "r"(addr));
}

__device__ __forceinline__ uint32_t pack_h2(float x, float y) {
    __half2 h = __floats2half2_rn(x, y);
    return *reinterpret_cast<uint32_t*>(&h);
}

__device__ __forceinline__ void split_pack_h2(float x, float y,
                                              uint32_t& hi, uint32_t& lo) {
    __half2 h = __floats2half2_rn(x, y);
    float xl = x - __half2float(h.x);
    float yl = y - __half2float(h.y);
    __half2 l = __floats2half2_rn(xl, yl);
    hi = *reinterpret_cast<uint32_t*>(&h);
    lo = *reinterpret_cast<uint32_t*>(&l);
}

// 8 mask bits (pair s at bits 2s,2s+1) -> 4 half2 AND-words
__device__ __forceinline__ void expand4(uint32_t byte, uint32_t w[4]) {
    uint32_t lo = ((byte & 0xFu) * 0x00204081u) & 0x01010101u;
    uint32_t hi = (((byte >> 4) & 0xFu) * 0x00204081u) & 0x01010101u;
    lo *= 0xFFu;
    hi *= 0xFFu;
    w[0] = __byte_perm(lo, lo, 0x1100);
    w[1] = __byte_perm(lo, lo, 0x3322);
    w[2] = __byte_perm(hi, hi, 0x1100);
    w[3] = __byte_perm(hi, hi, 0x3322);
}

__device__ __forceinline__ void cp16(void* dst, const void* src) {
    uint32_t d = (uint32_t)__cvta_generic_to_shared(dst);
    asm volatile("cp.async.cg.shared.global [%0], [%1], 16;" :: "r"(d), "l"(src));
}
__device__ __forceinline__ void cp4(void* dst, const void* src) {
    uint32_t d = (uint32_t)__cvta_generic_to_shared(dst);
    asm volatile("cp.async.ca.shared.global [%0], [%1], 4;" :: "r"(d), "l"(src));
}
#define CP_COMMIT() asm volatile("cp.async.commit_group;")
#define CP_WAIT0()  asm volatile("cp.async.wait_group 0;")

// ============ fused preprocessing ============
__global__ void prep_all(const float* __restrict__ k, const float* __restrict__ v,
                         const int* __restrict__ m)
{
    __shared__ float st[64][33];
    const int bid = blockIdx.x;
    const int tid = threadIdx.x;

    if (bid < PREP_KBLK) {
        int idx = bid * 256 + tid;   // float4 index
        float4 t = reinterpret_cast<const float4*>(k)[idx];
        uint32_t h0 = pack_h2(t.x * SCALE_LOG2, t.y * SCALE_LOG2);
        uint32_t h1 = pack_h2(t.z * SCALE_LOG2, t.w * SCALE_LOG2);
        reinterpret_cast<uint2*>(g_kh)[idx] = make_uint2(h0, h1);
    } else if (bid < PREP_KBLK + PREP_VBLK) {
        const int vb = bid - PREP_KBLK;
        const int bh = vb >> 5, j0 = (vb & 31) * 64;
        const float* vbp = v + (long)bh * Ldim * Edim + (long)j0 * Edim;
        #pragma unroll
        for (int it = 0; it < 8; ++it) {
            int item = tid + 256 * it;
            int key = item >> 5, e = item & 31;
            st[key][e] = vbp[key * Edim + e];
        }
        __syncthreads();
        __half* oh = g_vt + (long)bh * Edim * Ldim + j0;
        #pragma unroll
        for (int it = 0; it < 8; ++it) {
            int item = tid + 256 * it;
            int e = item >> 6, key = item & 63;
            oh[(long)e * Ldim + key] = __float2half_rn(st[key][e]);
        }
    } else {
        const int row = bid - (PREP_KBLK + PREP_VBLK);   // b*L + i
        const int j8 = tid >> 3, t = (tid >> 1) & 3, ab = tid & 1;
        const int* mr = m + (long)row * Ldim + j8 * 64 + 2 * t + 8 * ab;
        uint32_t byte = 0;
        #pragma unroll
        for (int s = 0; s < 4; ++s) {
            int2 mm = *(const int2*)(mr + 16 * s);
            byte |= (mm.x != 0 ? 1u : 0u) << (2 * s);
            byte |= (mm.y != 0 ? 1u : 0u) << (2 * s + 1);
        }
        g_mpack[((long)row * 32 + j8) * 8 + t * 2 + ab] = (uint8_t)byte;
    }
}

// ============ attention ============

__global__ __launch_bounds__(128, 5)
void attn_kernel(const float* __restrict__ gq, float* __restrict__ gout)
{
    __shared__ __align__(16) __half kh_s[2][TK * KST];
    __shared__ __align__(16) __half v_s[2][VROWS * VST];
    __shared__ __align__(8) uint8_t m_s[2][TQ * 8];

    const int tid = threadIdx.x;
    const int w = tid >> 5, lane = tid & 31;
    const int g = lane >> 2, t = lane & 3;

    const int qt = blockIdx.x, h = blockIdx.y, b = blockIdx.z;
    const int i0 = qt * TQ;

    const long bh = (long)(b * Hdim + h) * Ldim * Edim;
    const float* qb = gq + bh + (long)i0 * Edim;
    const __half* KHg = g_kh + bh;
    const __half* Vg = g_vt + bh;          // [e][key]
    const uint8_t* MBg = g_mpack + ((long)(b * Ldim + i0)) * 32 * 8;

    // ---- Q fragments (persistent, fp16 hi/lo; scale folded into K) ----
    const int r0 = w * 16 + g;
    uint32_t Qh0[4], Ql0[4], Qh1[4], Ql1[4];
    {
        const float* q0 = qb + (long)r0 * Edim;
        const float* q1 = qb + (long)(r0 + 8) * Edim;
        #pragma unroll
        for (int ks = 0; ks < 2; ++ks) {
            uint32_t* Qh = ks ? Qh1 : Qh0;
            uint32_t* Ql = ks ? Ql1 : Ql0;
            float2 x0 = *(const float2*)(q0 + 2 * t + 16 * ks);
            float2 x1 = *(const float2*)(q1 + 2 * t + 16 * ks);
            float2 x2 = *(const float2*)(q0 + 2 * t + 8 + 16 * ks);
            float2 x3 = *(const float2*)(q1 + 2 * t + 8 + 16 * ks);
            split_pack_h2(x0.x, x0.y, Qh[0], Ql[0]);
            split_pack_h2(x1.x, x1.y, Qh[1], Ql[1]);
            split_pack_h2(x2.x, x2.y, Qh[2], Ql[2]);
            split_pack_h2(x3.x, x3.y, Qh[3], Ql[3]);
        }
    }

    // ldmatrix base addresses (per stage)
    uint32_t kbase[2], vbase[2];
    {
        uint32_t koff = ((lane & 7) * KST + (lane >> 3) * 8) * 2;
        uint32_t voff = ((lane & 7) * VST + (lane >> 3) * 8) * 2;
        kbase[0] = (uint32_t)__cvta_generic_to_shared(&kh_s[0][0]) + koff;
        kbase[1] = (uint32_t)__cvta_generic_to_shared(&kh_s[1][0]) + koff;
        vbase[0] = (uint32_t)__cvta_generic_to_shared(&v_s[0][0]) + voff;
        vbase[1] = (uint32_t)__cvta_generic_to_shared(&v_s[1][0]) + voff;
    }

    // O[0..3] = P*V output columns; l accumulated in fp32 registers
    float O[4][4];
    #pragma unroll
    for (int n = 0; n < 4; ++n)
        #pragma unroll
        for (int j = 0; j < 4; ++j) O[n][j] = 0.0f;
    float l0 = 0.0f, l1 = 0.0f;

    auto load_tile = [&](int st, int jt) {
        const int j0 = jt * TK;
        #pragma unroll
        for (int it = 0; it < 2; ++it) {
            int item = tid + 128 * it;
            int key = item >> 2, seg = item & 3;
            cp16(&kh_s[st][key * KST + seg * 8],
                 KHg + (long)(j0 + key) * Edim + seg * 8);
        }
        #pragma unroll
        for (int it = 0; it < 2; ++it) {
            int item = tid + 128 * it;
            int e = item >> 3, seg = item & 7;
            cp16(&v_s[st][e * VST + seg * 8], Vg + (long)e * Ldim + j0 + seg * 8);
        }
        {
            int row = tid >> 1, half = tid & 1;
            cp4(&m_s[st][row * 8 + half * 4],
                MBg + (long)row * 32 * 8 + jt * 8 + half * 4);
        }
    };

    load_tile(0, 0);
    CP_COMMIT();

    for (int jt = 0; jt < NT; ++jt) {
        CP_WAIT0();
        __syncthreads();
        if (jt + 1 < NT) { load_tile((jt + 1) & 1, jt + 1); CP_COMMIT(); }

        const int st = jt & 1;

        // mask rows (prefetch; expand is cheap, ALU not binding)
        const uint16_t mr0 = *(const uint16_t*)&m_s[st][r0 * 8 + 2 * t];
        const uint16_t mr1 = *(const uint16_t*)&m_s[st][(r0 + 8) * 8 + 2 * t];
        uint32_t wA0[4], wB0[4], wA1[4], wB1[4];
        expand4(mr0 & 0xFFu, wA0);
        expand4(mr0 >> 8, wB0);
        expand4(mr1 & 0xFFu, wA1);
        expand4(mr1 >> 8, wB1);

        // ==== two self-contained phases: ph=0 -> n-groups 0-3, chunks 0-1;
        //                                 ph=1 -> n-groups 4-7, chunks 2-3 ====
        #pragma unroll
        for (int ph = 0; ph < 2; ++ph) {
            // ---- GEMM1 half: S for 4 key n-groups ----
            float S[4][4];
            #pragma unroll
            for (int n = 0; n < 4; ++n)
                #pragma unroll
                for (int j = 0; j < 4; ++j) S[n][j] = 0.0f;

            #pragma unroll
            for (int n = 0; n < 4; ++n) {
                uint32_t b0, b1, b2, b3;
                ldsm4(b0, b1, b2, b3,
                      kbase[st] + (4 * ph + n) * (8 * KST * 2));
                mma_f16(S[n], Qh0, b0, b1);
                mma_f16(S[n], Qh1, b2, b3);
                mma_f16(S[n], Ql0, b0, b1);
                mma_f16(S[n], Ql1, b2, b3);
            }

            // ---- softmax chunk-pair ----
            uint32_t Ap[2][4];
            #pragma unroll
            for (int c = 0; c < 2; ++c) {
                const int s = 2 * ph + c;
                Ap[c][0] = h2ex2(pack_h2(S[2 * c][0], S[2 * c][1])) & wA0[s];
                Ap[c][1] = h2ex2(pack_h2(S[2 * c][2], S[2 * c][3])) & wA1[s];
                Ap[c][2] = h2ex2(pack_h2(S[2 * c + 1][0], S[2 * c + 1][1])) & wB0[s];
                Ap[c][3] = h2ex2(pack_h2(S[2 * c + 1][2], S[2 * c + 1][3])) & wB1[s];
            }

            // ---- l: HADD2 trees (row r0: [0],[2]; row r0+8: [1],[3]) ----
            {
                __half2 a0 = __hadd2(*(__half2*)&Ap[0][0], *(__half2*)&Ap[0][2]);
                __half2 a1 = __hadd2(*(__half2*)&Ap[1][0], *(__half2*)&Ap[1][2]);
                __half2 b0 = __hadd2(*(__half2*)&Ap[0][1], *(__half2*)&Ap[0][3]);
                __half2 b1 = __hadd2(*(__half2*)&Ap[1][1], *(__half2*)&Ap[1][3]);
                float2 fa = __half22float2(__hadd2(a0, a1));
                float2 fb = __half22float2(__hadd2(b0, b1));
                l0 += fa.x + fa.y;
                l1 += fb.x + fb.y;
            }

            // ---- GEMM2 k-half: 4 output n-groups x 2 chunks ----
            #pragma unroll
            for (int n = 0; n < 4; ++n) {
                uint32_t c0, c1, c2, c3;
                ldsm4(c0, c1, c2, c3,
                      vbase[st] + n * (8 * VST * 2) + ph * 64);
                mma_f16(O[n], Ap[0], c0, c1);
                mma_f16(O[n], Ap[1], c2, c3);
            }
        }
    }

    // ---- finalize: reduce l across the 4 t-lanes of the quad ----
    l0 += __shfl_xor_sync(0xffffffffu, l0, 1);
    l0 += __shfl_xor_sync(0xffffffffu, l0, 2);
    l1 += __shfl_xor_sync(0xffffffffu, l1, 1);
    l1 += __shfl_xor_sync(0xffffffffu, l1, 2);
    const float inv0 = (l0 > 0.0f) ? (1.0f / l0) : 0.0f;
    const float inv1 = (l1 > 0.0f) ? (1.0f / l1) : 0.0f;

    float* ob0 = gout + bh + (long)(i0 + r0) * Edim;
    float* ob1 = gout + bh + (long)(i0 + r0 + 8) * Edim;
    #pragma unroll
    for (int n = 0; n < 4; ++n) {
        float2 o0 = make_float2(O[n][0] * inv0, O[n][1] * inv0);
        float2 o1 = make_float2(O[n][2] * inv1, O[n][3] * inv1);
        *(float2*)(ob0 + 8 * n + 2 * t) = o0;
        *(float2*)(ob1 + 8 * n + 2 * t) = o1;
    }
}

extern "C" void kernel_launch(void* const* d_in, const int* in_sizes, int n_in,
                              void* d_out, int out_size)
{
    const float* q = (const float*)d_in[0];
    const float* k = (const float*)d_in[1];
    const float* v = (const float*)d_in[2];
    const int*   m = (const int*)d_in[3];
    float* out = (float*)d_out;

    prep_all<<<PREP_KBLK + PREP_VBLK + PREP_MBLK, 256>>>(k, v, m);

    dim3 grid(Ldim / TQ, Hdim, Bdim);
    attn_kernel<<<grid, 128>>>(q, out);
}

// round 15
// speedup vs baseline: 1.0486x; 1.0486x over previous
#include <cuda_runtime.h>
#include <cuda_bf16.h>
#include <cuda_fp16.h>
#include <cstdint>

// Flash-attention, no-online-softmax (scores bounded -> fixed exp base).
// GEMM1 = fp16 2-term (Q hi/lo vs fp16 K, scale folded into K), ldmatrix B-frags,
// issued as ONE independent 32-HMMA stream (max ILP). GEMM2 = fp16 single-term,
// 4 output n-groups. l = sum(p) via HADD2 tree on masked P words (fp32 across
// tiles) -- no tensor-core ones-column. Softmax interleaved with GEMM2 at
// k-chunk granularity (phase A: chunks 0-1, phase B: chunks 2-3).
// Fused preprocessing. B=4,H=8,L=2048,E=32.
// CTA: 128 thr (4 warps), TQ=64 (16 rows/warp), TK=64.

constexpr int Bdim = 4, Hdim = 8, Ldim = 2048, Edim = 32;
constexpr int TQ = 64, TK = 64, NT = Ldim / TK;
constexpr float SCALE_LOG2 = 0.25507312986795477f;  // log2(e)/TEMPERATURE
constexpr int KST = 40;   // k tile row stride (half): ldmatrix conflict-free
constexpr int VST = 72;   // vT tile row stride (half): ldmatrix conflict-free
constexpr int VROWS = 32; // data rows only (no ones column)

// prep grid split
constexpr int PREP_KBLK = (Bdim * Hdim * Ldim * Edim / 4) / 256;  // 2048
constexpr int PREP_VBLK = (Bdim * Hdim) * (Ldim / 64);            // 1024
constexpr int PREP_MBLK = Bdim * Ldim;                            // 8192

// ---- preprocessed scratch ----
__device__ __half   g_kh[Bdim * Hdim * Ldim * Edim];      // scaled fp16 K
__device__ __half   g_vt[Bdim * Hdim * Edim * Ldim];      // [b,h,e,key] fp16
__device__ uint8_t  g_mpack[(long)Bdim * Ldim * 32 * 8];  // [b*L+i][j8][t*2+ab]

__device__ __forceinline__ uint32_t h2ex2(uint32_t x) {
    uint32_t y;
    asm("ex2.approx.f16x2 %0, %1;" : "=r"(y) : "r"(x));
    return y;
}

__device__ __forceinline__ void mma_f16(float c[4], const uint32_t a[4],
                                        uint32_t b0, uint32_t b1) {
    asm volatile(
        "mma.sync.aligned.m16n8k16.row.col.f32.f16.f16.f32 "
        "{%0,%1,%2,%3},{%4,%5,%6,%7},{%8,%9},{%0,%1,%2,%3};"
        : "+f"(c[0]), "+f"(c[1]), "+f"(c[2]), "+f"(c[3])
        : "r"(a[0]), "r"(a[1]), "r"(a[2]), "r"(a[3]), "r"(b0), "r"(b1));
}

__device__ __forceinline__ void ldsm4(uint32_t& a, uint32_t& b, uint32_t& c,
                                      uint32_t& d, uint32_t addr) {
    asm volatile(
        "ldmatrix.sync.aligned.m8n8.x4.shared.b16 {%0,%1,%2,%3}, [%4];"
        : "=r"(a), "=r"(b), "=r"(c), "=r"(d) : "r"(addr));
}

__device__ __forceinline__ uint32_t pack_h2(float x, float y) {
    __half2 h = __floats2half2_rn(x, y);
    return *reinterpret_cast<uint32_t*>(&h);
}

__device__ __forceinline__ void split_pack_h2(float x, float y,
                                              uint32_t& hi, uint32_t& lo) {
    __half2 h = __floats2half2_rn(x, y);
    float xl = x - __half2float(h.x);
    float yl = y - __half2float(h.y);
    __half2 l = __floats2half2_rn(xl, yl);
    hi = *reinterpret_cast<uint32_t*>(&h);
    lo = *reinterpret_cast<uint32_t*>(&l);
}

// 8 mask bits (pair s at bits 2s,2s+1) -> 4 half2 AND-words
__device__ __forceinline__ void expand4(uint32_t byte, uint32_t w[4]) {
    uint32_t lo = ((byte & 0xFu) * 0x00204081u) & 0x01010101u;
    uint32_t hi = (((byte >> 4) & 0xFu) * 0x00204081u) & 0x01010101u;
    lo *= 0xFFu;
    hi *= 0xFFu;
    w[0] = __byte_perm(lo, lo, 0x1100);
    w[1] = __byte_perm(lo, lo, 0x3322);
    w[2] = __byte_perm(hi, hi, 0x1100);
    w[3] = __byte_perm(hi, hi, 0x3322);
}

__device__ __forceinline__ void cp16(void* dst, const void* src) {
    uint32_t d = (uint32_t)__cvta_generic_to_shared(dst);
    asm volatile("cp.async.cg.shared.global [%0], [%1], 16;" :: "r"(d), "l"(src));
}
__device__ __forceinline__ void cp4(void* dst, const void* src) {
    uint32_t d = (uint32_t)__cvta_generic_to_shared(dst);
    asm volatile("cp.async.ca.shared.global [%0], [%1], 4;" :: "r"(d), "l"(src));
}
#define CP_COMMIT() asm volatile("cp.async.commit_group;")
#define CP_WAIT0()  asm volatile("cp.async.wait_group 0;")

// ============ fused preprocessing ============
__global__ void prep_all(const float* __restrict__ k, const float* __restrict__ v,
                         const int* __restrict__ m)
{
    __shared__ float st[64][33];
    const int bid = blockIdx.x;
    const int tid = threadIdx.x;

    if (bid < PREP_KBLK) {
        int idx = bid * 256 + tid;   // float4 index
        float4 t = reinterpret_cast<const float4*>(k)[idx];
        uint32_t h0 = pack_h2(t.x * SCALE_LOG2, t.y * SCALE_LOG2);
        uint32_t h1 = pack_h2(t.z * SCALE_LOG2, t.w * SCALE_LOG2);
        reinterpret_cast<uint2*>(g_kh)[idx] = make_uint2(h0, h1);
    } else if (bid < PREP_KBLK + PREP_VBLK) {
        const int vb = bid - PREP_KBLK;
        const int bh = vb >> 5, j0 = (vb & 31) * 64;
        const float* vbp = v + (long)bh * Ldim * Edim + (long)j0 * Edim;
        #pragma unroll
        for (int it = 0; it < 8; ++it) {
            int item = tid + 256 * it;
            int key = item >> 5, e = item & 31;
            st[key][e] = vbp[key * Edim + e];
        }
        __syncthreads();
        __half* oh = g_vt + (long)bh * Edim * Ldim + j0;
        #pragma unroll
        for (int it = 0; it < 8; ++it) {
            int item = tid + 256 * it;
            int e = item >> 6, key = item & 63;
            oh[(long)e * Ldim + key] = __float2half_rn(st[key][e]);
        }
    } else {
        const int row = bid - (PREP_KBLK + PREP_VBLK);   // b*L + i
        const int j8 = tid >> 3, t = (tid >> 1) & 3, ab = tid & 1;
        const int* mr = m + (long)row * Ldim + j8 * 64 + 2 * t + 8 * ab;
        uint32_t byte = 0;
        #pragma unroll
        for (int s = 0; s < 4; ++s) {
            int2 mm = *(const int2*)(mr + 16 * s);
            byte |= (mm.x != 0 ? 1u : 0u) << (2 * s);
            byte |= (mm.y != 0 ? 1u : 0u) << (2 * s + 1);
        }
        g_mpack[((long)row * 32 + j8) * 8 + t * 2 + ab] = (uint8_t)byte;
    }
}

// ============ attention ============

__global__ __launch_bounds__(128, 4)
void attn_kernel(const float* __restrict__ gq, float* __restrict__ gout)
{
    __shared__ __align__(16) __half kh_s[2][TK * KST];
    __shared__ __align__(16) __half v_s[2][VROWS * VST];
    __shared__ __align__(8) uint8_t m_s[2][TQ * 8];

    const int tid = threadIdx.x;
    const int w = tid >> 5, lane = tid & 31;
    const int g = lane >> 2, t = lane & 3;

    const int qt = blockIdx.x, h = blockIdx.y, b = blockIdx.z;
    const int i0 = qt * TQ;

    const long bh = (long)(b * Hdim + h) * Ldim * Edim;
    const float* qb = gq + bh + (long)i0 * Edim;
    const __half* KHg = g_kh + bh;
    const __half* Vg = g_vt + bh;          // [e][key]
    const uint8_t* MBg = g_mpack + ((long)(b * Ldim + i0)) * 32 * 8;

    // ---- Q fragments (persistent, fp16 hi/lo; scale folded into K) ----
    const int r0 = w * 16 + g;
    uint32_t Qh0[4], Ql0[4], Qh1[4], Ql1[4];
    {
        const float* q0 = qb + (long)r0 * Edim;
        const float* q1 = qb + (long)(r0 + 8) * Edim;
        #pragma unroll
        for (int ks = 0; ks < 2; ++ks) {
            uint32_t* Qh = ks ? Qh1 : Qh0;
            uint32_t* Ql = ks ? Ql1 : Ql0;
            float2 x0 = *(const float2*)(q0 + 2 * t + 16 * ks);
            float2 x1 = *(const float2*)(q1 + 2 * t + 16 * ks);
            float2 x2 = *(const float2*)(q0 + 2 * t + 8 + 16 * ks);
            float2 x3 = *(const float2*)(q1 + 2 * t + 8 + 16 * ks);
            split_pack_h2(x0.x, x0.y, Qh[0], Ql[0]);
            split_pack_h2(x1.x, x1.y, Qh[1], Ql[1]);
            split_pack_h2(x2.x, x2.y, Qh[2], Ql[2]);
            split_pack_h2(x3.x, x3.y, Qh[3], Ql[3]);
        }
    }

    // ldmatrix base addresses (per stage)
    uint32_t kbase[2], vbase[2];
    {
        uint32_t koff = ((lane & 7) * KST + (lane >> 3) * 8) * 2;
        uint32_t voff = ((lane & 7) * VST + (lane >> 3) * 8) * 2;
        kbase[0] = (uint32_t)__cvta_generic_to_shared(&kh_s[0][0]) + koff;
        kbase[1] = (uint32_t)__cvta_generic_to_shared(&kh_s[1][0]) + koff;
        vbase[0] = (uint32_t)__cvta_generic_to_shared(&v_s[0][0]) + voff;
        vbase[1] = (uint32_t)__cvta_generic_to_shared(&v_s[1][0]) + voff;
    }

    // O[0..3] = P*V output columns; l accumulated in fp32 registers
    float O[4][4];
    #pragma unroll
    for (int n = 0; n < 4; ++n)
        #pragma unroll
        for (int j = 0; j < 4; ++j) O[n][j] = 0.0f;
    float l0 = 0.0f, l1 = 0.0f;

    auto load_tile = [&](int st, int jt) {
        const int j0 = jt * TK;
        #pragma unroll
        for (int it = 0; it < 2; ++it) {
            int item = tid + 128 * it;
            int key = item >> 2, seg = item & 3;
            cp16(&kh_s[st][key * KST + seg * 8],
                 KHg + (long)(j0 + key) * Edim + seg * 8);
        }
        #pragma unroll
        for (int it = 0; it < 2; ++it) {
            int item = tid + 128 * it;
            int e = item >> 3, seg = item & 7;
            cp16(&v_s[st][e * VST + seg * 8], Vg + (long)e * Ldim + j0 + seg * 8);
        }
        {
            int row = tid >> 1, half = tid & 1;
            cp4(&m_s[st][row * 8 + half * 4],
                MBg + (long)row * 32 * 8 + jt * 8 + half * 4);
        }
    };

    load_tile(0, 0);
    CP_COMMIT();

    #pragma unroll 2
    for (int jt = 0; jt < NT; ++jt) {
        CP_WAIT0();
        __syncthreads();
        if (jt + 1 < NT) { load_tile((jt + 1) & 1, jt + 1); CP_COMMIT(); }

        const int st = jt & 1;

        // ---- prefetch mask rows (LDS latency overlaps GEMM1) ----
        const uint16_t mr0 = *(const uint16_t*)&m_s[st][r0 * 8 + 2 * t];
        const uint16_t mr1 = *(const uint16_t*)&m_s[st][(r0 + 8) * 8 + 2 * t];

        // ---- GEMM1: S(16x64) = Qh*K + Ql*K, one independent HMMA stream ----
        float S[8][4];
        #pragma unroll
        for (int n = 0; n < 8; ++n)
            #pragma unroll
            for (int j = 0; j < 4; ++j) S[n][j] = 0.0f;

        #pragma unroll
        for (int n = 0; n < 8; ++n) {
            uint32_t b0, b1, b2, b3;
            ldsm4(b0, b1, b2, b3, kbase[st] + n * (8 * KST * 2));
            mma_f16(S[n], Qh0, b0, b1);
            mma_f16(S[n], Qh1, b2, b3);
            mma_f16(S[n], Ql0, b0, b1);
            mma_f16(S[n], Ql1, b2, b3);
        }

        // ---- mask AND-words ----
        uint32_t wA0[4], wB0[4], wA1[4], wB1[4];
        expand4(mr0 & 0xFFu, wA0);
        expand4(mr0 >> 8, wB0);
        expand4(mr1 & 0xFFu, wA1);
        expand4(mr1 >> 8, wB1);

        // ==== phase A: softmax chunks 0-1, l-tree, GEMM2 k-half 0 ====
        uint32_t Ap[4][4];
        #pragma unroll
        for (int s = 0; s < 2; ++s) {
            Ap[s][0] = h2ex2(pack_h2(S[2 * s][0], S[2 * s][1])) & wA0[s];
            Ap[s][1] = h2ex2(pack_h2(S[2 * s][2], S[2 * s][3])) & wA1[s];
            Ap[s][2] = h2ex2(pack_h2(S[2 * s + 1][0], S[2 * s + 1][1])) & wB0[s];
            Ap[s][3] = h2ex2(pack_h2(S[2 * s + 1][2], S[2 * s + 1][3])) & wB1[s];
        }
        {
            __half2 a0 = __hadd2(*(__half2*)&Ap[0][0], *(__half2*)&Ap[0][2]);
            __half2 a1 = __hadd2(*(__half2*)&Ap[1][0], *(__half2*)&Ap[1][2]);
            __half2 b0 = __hadd2(*(__half2*)&Ap[0][1], *(__half2*)&Ap[0][3]);
            __half2 b1 = __hadd2(*(__half2*)&Ap[1][1], *(__half2*)&Ap[1][3]);
            float2 fa = __half22float2(__hadd2(a0, a1));
            float2 fb = __half22float2(__hadd2(b0, b1));
            l0 += fa.x + fa.y;
            l1 += fb.x + fb.y;
        }
        #pragma unroll
        for (int n = 0; n < 4; ++n) {
            uint32_t c0, c1, c2, c3;
            ldsm4(c0, c1, c2, c3, vbase[st] + n * (8 * VST * 2));
            mma_f16(O[n], Ap[0], c0, c1);
            mma_f16(O[n], Ap[1], c2, c3);
        }

        // ==== phase B: softmax chunks 2-3, l-tree, GEMM2 k-half 1 ====
        #pragma unroll
        for (int s = 2; s < 4; ++s) {
            Ap[s][0] = h2ex2(pack_h2(S[2 * s][0], S[2 * s][1])) & wA0[s];
            Ap[s][1] = h2ex2(pack_h2(S[2 * s][2], S[2 * s][3])) & wA1[s];
            Ap[s][2] = h2ex2(pack_h2(S[2 * s + 1][0], S[2 * s + 1][1])) & wB0[s];
            Ap[s][3] = h2ex2(pack_h2(S[2 * s + 1][2], S[2 * s + 1][3])) & wB1[s];
        }
        {
            __half2 a0 = __hadd2(*(__half2*)&Ap[2][0], *(__half2*)&Ap[2][2]);
            __half2 a1 = __hadd2(*(__half2*)&Ap[3][0], *(__half2*)&Ap[3][2]);
            __half2 b0 = __hadd2(*(__half2*)&Ap[2][1], *(__half2*)&Ap[2][3]);
            __half2 b1 = __hadd2(*(__half2*)&Ap[3][1], *(__half2*)&Ap[3][3]);
            float2 fa = __half22float2(__hadd2(a0, a1));
            float2 fb = __half22float2(__hadd2(b0, b1));
            l0 += fa.x + fa.y;
            l1 += fb.x + fb.y;
        }
        #pragma unroll
        for (int n = 0; n < 4; ++n) {
            uint32_t c0, c1, c2, c3;
            ldsm4(c0, c1, c2, c3, vbase[st] + n * (8 * VST * 2) + 64);
            mma_f16(O[n], Ap[2], c0, c1);
            mma_f16(O[n], Ap[3], c2, c3);
        }
    }

    // ---- finalize: reduce l across the 4 t-lanes of the quad ----
    l0 += __shfl_xor_sync(0xffffffffu, l0, 1);
    l0 += __shfl_xor_sync(0xffffffffu, l0, 2);
    l1 += __shfl_xor_sync(0xffffffffu, l1, 1);
    l1 += __shfl_xor_sync(0xffffffffu, l1, 2);
    const float inv0 = (l0 > 0.0f) ? (1.0f / l0) : 0.0f;
    const float inv1 = (l1 > 0.0f) ? (1.0f / l1) : 0.0f;

    float* ob0 = gout + bh + (long)(i0 + r0) * Edim;
    float* ob1 = gout + bh + (long)(i0 + r0 + 8) * Edim;
    #pragma unroll
    for (int n = 0; n < 4; ++n) {
        float2 o0 = make_float2(O[n][0] * inv0, O[n][1] * inv0);
        float2 o1 = make_float2(O[n][2] * inv1, O[n][3] * inv1);
        *(float2*)(ob0 + 8 * n + 2 * t) = o0;
        *(float2*)(ob1 + 8 * n + 2 * t) = o1;
    }
}

extern "C" void kernel_launch(void* const* d_in, const int* in_sizes, int n_in,
                              void* d_out, int out_size)
{
    const float* q = (const float*)d_in[0];
    const float* k = (const float*)d_in[1];
    const float* v = (const float*)d_in[2];
    const int*   m = (const int*)d_in[3];
    float* out = (float*)d_out;

    prep_all<<<PREP_KBLK + PREP_VBLK + PREP_MBLK, 256>>>(k, v, m);

    dim3 grid(Ldim / TQ, Hdim, Bdim);
    attn_kernel<<<grid, 128>>>(q, out);
}

// round 16
// speedup vs baseline: 1.1865x; 1.1315x over previous
#include <cuda_runtime.h>
#include <cuda_bf16.h>
#include <cuda_fp16.h>
#include <cstdint>

// Flash-attention, no-online-softmax (scores bounded -> fixed exp base).
// GEMM1 = fp16 SINGLE-term (fp16 Q x fp16 K, scale folded into K): 16 HMMA/tile.
// ex2 in fp32 MUFU (removes the f16x2-ex2 rounding error term, paying for the
// dropped Q-lo GEMM1 term). GEMM2 = fp16 single-term, 4 output n-groups.
// l = sum(p) via HADD2 tree on masked P words (fp32 across tiles).
// Softmax interleaved with GEMM2 at k-chunk granularity. Fused preprocessing.
// B=4,H=8,L=2048,E=32. CTA: 128 thr (4 warps), TQ=64 (16 rows/warp), TK=64.

constexpr int Bdim = 4, Hdim = 8, Ldim = 2048, Edim = 32;
constexpr int TQ = 64, TK = 64, NT = Ldim / TK;
constexpr float SCALE_LOG2 = 0.25507312986795477f;  // log2(e)/TEMPERATURE
constexpr int KST = 40;   // k tile row stride (half): ldmatrix conflict-free
constexpr int VST = 72;   // vT tile row stride (half): ldmatrix conflict-free
constexpr int VROWS = 32; // data rows only

// prep grid split
constexpr int PREP_KBLK = (Bdim * Hdim * Ldim * Edim / 4) / 256;  // 2048
constexpr int PREP_VBLK = (Bdim * Hdim) * (Ldim / 64);            // 1024
constexpr int PREP_MBLK = Bdim * Ldim;                            // 8192

// ---- preprocessed scratch ----
__device__ __half   g_kh[Bdim * Hdim * Ldim * Edim];      // scaled fp16 K
__device__ __half   g_vt[Bdim * Hdim * Edim * Ldim];      // [b,h,e,key] fp16
__device__ uint8_t  g_mpack[(long)Bdim * Ldim * 32 * 8];  // [b*L+i][j8][t*2+ab]

__device__ __forceinline__ float ex2f(float x) {
    float y;
    asm("ex2.approx.ftz.f32 %0, %1;" : "=f"(y) : "f"(x));
    return y;
}

__device__ __forceinline__ void mma_f16(float c[4], const uint32_t a[4],
                                        uint32_t b0, uint32_t b1) {
    asm volatile(
        "mma.sync.aligned.m16n8k16.row.col.f32.f16.f16.f32 "
        "{%0,%1,%2,%3},{%4,%5,%6,%7},{%8,%9},{%0,%1,%2,%3};"
        : "+f"(c[0]), "+f"(c[1]), "+f"(c[2]), "+f"(c[3])
        : "r"(a[0]), "r"(a[1]), "r"(a[2]), "r"(a[3]), "r"(b0), "r"(b1));
}

__device__ __forceinline__ void ldsm4(uint32_t& a, uint32_t& b, uint32_t& c,
                                      uint32_t& d, uint32_t addr) {
    asm volatile(
        "ldmatrix.sync.aligned.m8n8.x4.shared.b16 {%0,%1,%2,%3}, [%4];"
        : "=r"(a), "=r"(b), "=r"(c), "=r"(d) : "r"(addr));
}

__device__ __forceinline__ uint32_t pack_h2(float x, float y) {
    __half2 h = __floats2half2_rn(x, y);
    return *reinterpret_cast<uint32_t*>(&h);
}

// 8 mask bits (pair s at bits 2s,2s+1) -> 4 half2 AND-words
__device__ __forceinline__ void expand4(uint32_t byte, uint32_t w[4]) {
    uint32_t lo = ((byte & 0xFu) * 0x00204081u) & 0x01010101u;
    uint32_t hi = (((byte >> 4) & 0xFu) * 0x00204081u) & 0x01010101u;
    lo *= 0xFFu;
    hi *= 0xFFu;
    w[0] = __byte_perm(lo, lo, 0x1100);
    w[1] = __byte_perm(lo, lo, 0x3322);
    w[2] = __byte_perm(hi, hi, 0x1100);
    w[3] = __byte_perm(hi, hi, 0x3322);
}

__device__ __forceinline__ void cp16(void* dst, const void* src) {
    uint32_t d = (uint32_t)__cvta_generic_to_shared(dst);
    asm volatile("cp.async.cg.shared.global [%0], [%1], 16;" :: "r"(d), "l"(src));
}
__device__ __forceinline__ void cp4(void* dst, const void* src) {
    uint32_t d = (uint32_t)__cvta_generic_to_shared(dst);
    asm volatile("cp.async.ca.shared.global [%0], [%1], 4;" :: "r"(d), "l"(src));
}
#define CP_COMMIT() asm volatile("cp.async.commit_group;")
#define CP_WAIT0()  asm volatile("cp.async.wait_group 0;")

// ============ fused preprocessing ============
__global__ void prep_all(const float* __restrict__ k, const float* __restrict__ v,
                         const int* __restrict__ m)
{
    __shared__ float st[64][33];
    const int bid = blockIdx.x;
    const int tid = threadIdx.x;

    if (bid < PREP_KBLK) {
        int idx = bid * 256 + tid;   // float4 index
        float4 t = reinterpret_cast<const float4*>(k)[idx];
        uint32_t h0 = pack_h2(t.x * SCALE_LOG2, t.y * SCALE_LOG2);
        uint32_t h1 = pack_h2(t.z * SCALE_LOG2, t.w * SCALE_LOG2);
        reinterpret_cast<uint2*>(g_kh)[idx] = make_uint2(h0, h1);
    } else if (bid < PREP_KBLK + PREP_VBLK) {
        const int vb = bid - PREP_KBLK;
        const int bh = vb >> 5, j0 = (vb & 31) * 64;
        const float* vbp = v + (long)bh * Ldim * Edim + (long)j0 * Edim;
        #pragma unroll
        for (int it = 0; it < 8; ++it) {
            int item = tid + 256 * it;
            int key = item >> 5, e = item & 31;
            st[key][e] = vbp[key * Edim + e];
        }
        __syncthreads();
        __half* oh = g_vt + (long)bh * Edim * Ldim + j0;
        #pragma unroll
        for (int it = 0; it < 8; ++it) {
            int item = tid + 256 * it;
            int e = item >> 6, key = item & 63;
            oh[(long)e * Ldim + key] = __float2half_rn(st[key][e]);
        }
    } else {
        const int row = bid - (PREP_KBLK + PREP_VBLK);   // b*L + i
        const int j8 = tid >> 3, t = (tid >> 1) & 3, ab = tid & 1;
        const int* mr = m + (long)row * Ldim + j8 * 64 + 2 * t + 8 * ab;
        uint32_t byte = 0;
        #pragma unroll
        for (int s = 0; s < 4; ++s) {
            int2 mm = *(const int2*)(mr + 16 * s);
            byte |= (mm.x != 0 ? 1u : 0u) << (2 * s);
            byte |= (mm.y != 0 ? 1u : 0u) << (2 * s + 1);
        }
        g_mpack[((long)row * 32 + j8) * 8 + t * 2 + ab] = (uint8_t)byte;
    }
}

// ============ attention ============

__global__ __launch_bounds__(128, 4)
void attn_kernel(const float* __restrict__ gq, float* __restrict__ gout)
{
    __shared__ __align__(16) __half kh_s[2][TK * KST];
    __shared__ __align__(16) __half v_s[2][VROWS * VST];
    __shared__ __align__(8) uint8_t m_s[2][TQ * 8];

    const int tid = threadIdx.x;
    const int w = tid >> 5, lane = tid & 31;
    const int g = lane >> 2, t = lane & 3;

    const int qt = blockIdx.x, h = blockIdx.y, b = blockIdx.z;
    const int i0 = qt * TQ;

    const long bh = (long)(b * Hdim + h) * Ldim * Edim;
    const float* qb = gq + bh + (long)i0 * Edim;
    const __half* KHg = g_kh + bh;
    const __half* Vg = g_vt + bh;          // [e][key]
    const uint8_t* MBg = g_mpack + ((long)(b * Ldim + i0)) * 32 * 8;

    // ---- Q fragments (persistent, single fp16; scale folded into K) ----
    const int r0 = w * 16 + g;
    uint32_t Q0[4], Q1[4];
    {
        const float* q0 = qb + (long)r0 * Edim;
        const float* q1 = qb + (long)(r0 + 8) * Edim;
        #pragma unroll
        for (int ks = 0; ks < 2; ++ks) {
            uint32_t* Qf = ks ? Q1 : Q0;
            float2 x0 = *(const float2*)(q0 + 2 * t + 16 * ks);
            float2 x1 = *(const float2*)(q1 + 2 * t + 16 * ks);
            float2 x2 = *(const float2*)(q0 + 2 * t + 8 + 16 * ks);
            float2 x3 = *(const float2*)(q1 + 2 * t + 8 + 16 * ks);
            Qf[0] = pack_h2(x0.x, x0.y);
            Qf[1] = pack_h2(x1.x, x1.y);
            Qf[2] = pack_h2(x2.x, x2.y);
            Qf[3] = pack_h2(x3.x, x3.y);
        }
    }

    // ldmatrix base addresses (per stage)
    uint32_t kbase[2], vbase[2];
    {
        uint32_t koff = ((lane & 7) * KST + (lane >> 3) * 8) * 2;
        uint32_t voff = ((lane & 7) * VST + (lane >> 3) * 8) * 2;
        kbase[0] = (uint32_t)__cvta_generic_to_shared(&kh_s[0][0]) + koff;
        kbase[1] = (uint32_t)__cvta_generic_to_shared(&kh_s[1][0]) + koff;
        vbase[0] = (uint32_t)__cvta_generic_to_shared(&v_s[0][0]) + voff;
        vbase[1] = (uint32_t)__cvta_generic_to_shared(&v_s[1][0]) + voff;
    }

    // O[0..3] = P*V output columns; l accumulated in fp32 registers
    float O[4][4];
    #pragma unroll
    for (int n = 0; n < 4; ++n)
        #pragma unroll
        for (int j = 0; j < 4; ++j) O[n][j] = 0.0f;
    float l0 = 0.0f, l1 = 0.0f;

    auto load_tile = [&](int st, int jt) {
        const int j0 = jt * TK;
        #pragma unroll
        for (int it = 0; it < 2; ++it) {
            int item = tid + 128 * it;
            int key = item >> 2, seg = item & 3;
            cp16(&kh_s[st][key * KST + seg * 8],
                 KHg + (long)(j0 + key) * Edim + seg * 8);
        }
        #pragma unroll
        for (int it = 0; it < 2; ++it) {
            int item = tid + 128 * it;
            int e = item >> 3, seg = item & 7;
            cp16(&v_s[st][e * VST + seg * 8], Vg + (long)e * Ldim + j0 + seg * 8);
        }
        {
            int row = tid >> 1, half = tid & 1;
            cp4(&m_s[st][row * 8 + half * 4],
                MBg + (long)row * 32 * 8 + jt * 8 + half * 4);
        }
    };

    load_tile(0, 0);
    CP_COMMIT();

    #pragma unroll 2
    for (int jt = 0; jt < NT; ++jt) {
        CP_WAIT0();
        __syncthreads();
        if (jt + 1 < NT) { load_tile((jt + 1) & 1, jt + 1); CP_COMMIT(); }

        const int st = jt & 1;

        // ---- prefetch mask rows (LDS latency overlaps GEMM1) ----
        const uint16_t mr0 = *(const uint16_t*)&m_s[st][r0 * 8 + 2 * t];
        const uint16_t mr1 = *(const uint16_t*)&m_s[st][(r0 + 8) * 8 + 2 * t];

        // ---- GEMM1: S(16x64) = Q*K, one independent HMMA stream ----
        float S[8][4];
        #pragma unroll
        for (int n = 0; n < 8; ++n)
            #pragma unroll
            for (int j = 0; j < 4; ++j) S[n][j] = 0.0f;

        #pragma unroll
        for (int n = 0; n < 8; ++n) {
            uint32_t b0, b1, b2, b3;
            ldsm4(b0, b1, b2, b3, kbase[st] + n * (8 * KST * 2));
            mma_f16(S[n], Q0, b0, b1);
            mma_f16(S[n], Q1, b2, b3);
        }

        // ---- mask AND-words ----
        uint32_t wA0[4], wB0[4], wA1[4], wB1[4];
        expand4(mr0 & 0xFFu, wA0);
        expand4(mr0 >> 8, wB0);
        expand4(mr1 & 0xFFu, wA1);
        expand4(mr1 >> 8, wB1);

        // ==== phase A: softmax chunks 0-1 (fp32 ex2), l-tree, GEMM2 half 0 ====
        uint32_t Ap[4][4];
        #pragma unroll
        for (int s = 0; s < 2; ++s) {
            Ap[s][0] = pack_h2(ex2f(S[2 * s][0]), ex2f(S[2 * s][1])) & wA0[s];
            Ap[s][1] = pack_h2(ex2f(S[2 * s][2]), ex2f(S[2 * s][3])) & wA1[s];
            Ap[s][2] = pack_h2(ex2f(S[2 * s + 1][0]), ex2f(S[2 * s + 1][1])) & wB0[s];
            Ap[s][3] = pack_h2(ex2f(S[2 * s + 1][2]), ex2f(S[2 * s + 1][3])) & wB1[s];
        }
        {
            __half2 a0 = __hadd2(*(__half2*)&Ap[0][0], *(__half2*)&Ap[0][2]);
            __half2 a1 = __hadd2(*(__half2*)&Ap[1][0], *(__half2*)&Ap[1][2]);
            __half2 b0 = __hadd2(*(__half2*)&Ap[0][1], *(__half2*)&Ap[0][3]);
            __half2 b1 = __hadd2(*(__half2*)&Ap[1][1], *(__half2*)&Ap[1][3]);
            float2 fa = __half22float2(__hadd2(a0, a1));
            float2 fb = __half22float2(__hadd2(b0, b1));
            l0 += fa.x + fa.y;
            l1 += fb.x + fb.y;
        }
        #pragma unroll
        for (int n = 0; n < 4; ++n) {
            uint32_t c0, c1, c2, c3;
            ldsm4(c0, c1, c2, c3, vbase[st] + n * (8 * VST * 2));
            mma_f16(O[n], Ap[0], c0, c1);
            mma_f16(O[n], Ap[1], c2, c3);
        }

        // ==== phase B: softmax chunks 2-3 (fp32 ex2), l-tree, GEMM2 half 1 ====
        #pragma unroll
        for (int s = 2; s < 4; ++s) {
            Ap[s][0] = pack_h2(ex2f(S[2 * s][0]), ex2f(S[2 * s][1])) & wA0[s];
            Ap[s][1] = pack_h2(ex2f(S[2 * s][2]), ex2f(S[2 * s][3])) & wA1[s];
            Ap[s][2] = pack_h2(ex2f(S[2 * s + 1][0]), ex2f(S[2 * s + 1][1])) & wB0[s];
            Ap[s][3] = pack_h2(ex2f(S[2 * s + 1][2]), ex2f(S[2 * s + 1][3])) & wB1[s];
        }
        {
            __half2 a0 = __hadd2(*(__half2*)&Ap[2][0], *(__half2*)&Ap[2][2]);
            __half2 a1 = __hadd2(*(__half2*)&Ap[3][0], *(__half2*)&Ap[3][2]);
            __half2 b0 = __hadd2(*(__half2*)&Ap[2][1], *(__half2*)&Ap[2][3]);
            __half2 b1 = __hadd2(*(__half2*)&Ap[3][1], *(__half2*)&Ap[3][3]);
            float2 fa = __half22float2(__hadd2(a0, a1));
            float2 fb = __half22float2(__hadd2(b0, b1));
            l0 += fa.x + fa.y;
            l1 += fb.x + fb.y;
        }
        #pragma unroll
        for (int n = 0; n < 4; ++n) {
            uint32_t c0, c1, c2, c3;
            ldsm4(c0, c1, c2, c3, vbase[st] + n * (8 * VST * 2) + 64);
            mma_f16(O[n], Ap[2], c0, c1);
            mma_f16(O[n], Ap[3], c2, c3);
        }
    }

    // ---- finalize: reduce l across the 4 t-lanes of the quad ----
    l0 += __shfl_xor_sync(0xffffffffu, l0, 1);
    l0 += __shfl_xor_sync(0xffffffffu, l0, 2);
    l1 += __shfl_xor_sync(0xffffffffu, l1, 1);
    l1 += __shfl_xor_sync(0xffffffffu, l1, 2);
    const float inv0 = (l0 > 0.0f) ? (1.0f / l0) : 0.0f;
    const float inv1 = (l1 > 0.0f) ? (1.0f / l1) : 0.0f;

    float* ob0 = gout + bh + (long)(i0 + r0) * Edim;
    float* ob1 = gout + bh + (long)(i0 + r0 + 8) * Edim;
    #pragma unroll
    for (int n = 0; n < 4; ++n) {
        float2 o0 = make_float2(O[n][0] * inv0, O[n][1] * inv0);
        float2 o1 = make_float2(O[n][2] * inv1, O[n][3] * inv1);
        *(float2*)(ob0 + 8 * n + 2 * t) = o0;
        *(float2*)(ob1 + 8 * n + 2 * t) = o1;
    }
}

extern "C" void kernel_launch(void* const* d_in, const int* in_sizes, int n_in,
                              void* d_out, int out_size)
{
    const float* q = (const float*)d_in[0];
    const float* k = (const float*)d_in[1];
    const float* v = (const float*)d_in[2];
    const int*   m = (const int*)d_in[3];
    float* out = (float*)d_out;

    prep_all<<<PREP_KBLK + PREP_VBLK + PREP_MBLK, 256>>>(k, v, m);

    dim3 grid(Ldim / TQ, Hdim, Bdim);
    attn_kernel<<<grid, 128>>>(q, out);
}

// round 17
// speedup vs baseline: 1.1920x; 1.0046x over previous
#include <cuda_runtime.h>
#include <cuda_bf16.h>
#include <cuda_fp16.h>
#include <cstdint>

// Flash-attention, no-online-softmax (scores bounded -> fixed exp base).
// GEMM1 = fp16 SINGLE-term (fp16 Q x fp16 K, scale folded into K): 16 HMMA/tile.
// Softmax: pack S -> half2, ex2.approx.f16x2 (16 MUFU/thread/tile), mask via
// bitwise AND. GEMM2 = fp16 single-term, 4 output n-groups. l = sum(p) via
// HADD2 tree on masked P (fp32 across tiles). Fused preprocessing.
// B=4,H=8,L=2048,E=32. CTA: 128 thr (4 warps), TQ=64 (16 rows/warp), TK=64.

constexpr int Bdim = 4, Hdim = 8, Ldim = 2048, Edim = 32;
constexpr int TQ = 64, TK = 64, NT = Ldim / TK;
constexpr float SCALE_LOG2 = 0.25507312986795477f;  // log2(e)/TEMPERATURE
constexpr int KST = 40;   // k tile row stride (half): ldmatrix conflict-free
constexpr int VST = 72;   // vT tile row stride (half): ldmatrix conflict-free
constexpr int VROWS = 32; // data rows only

// prep grid split
constexpr int PREP_KBLK = (Bdim * Hdim * Ldim * Edim / 4) / 256;  // 2048
constexpr int PREP_VBLK = (Bdim * Hdim) * (Ldim / 64);            // 1024
constexpr int PREP_MBLK = Bdim * Ldim;                            // 8192

// ---- preprocessed scratch ----
__device__ __half   g_kh[Bdim * Hdim * Ldim * Edim];      // scaled fp16 K
__device__ __half   g_vt[Bdim * Hdim * Edim * Ldim];      // [b,h,e,key] fp16
__device__ uint8_t  g_mpack[(long)Bdim * Ldim * 32 * 8];  // [b*L+i][j8][t*2+ab]

__device__ __forceinline__ uint32_t h2ex2(uint32_t x) {
    uint32_t y;
    asm("ex2.approx.f16x2 %0, %1;" : "=r"(y) : "r"(x));
    return y;
}

__device__ __forceinline__ void mma_f16(float c[4], const uint32_t a[4],
                                        uint32_t b0, uint32_t b1) {
    asm volatile(
        "mma.sync.aligned.m16n8k16.row.col.f32.f16.f16.f32 "
        "{%0,%1,%2,%3},{%4,%5,%6,%7},{%8,%9},{%0,%1,%2,%3};"
        : "+f"(c[0]), "+f"(c[1]), "+f"(c[2]), "+f"(c[3])
        : "r"(a[0]), "r"(a[1]), "r"(a[2]), "r"(a[3]), "r"(b0), "r"(b1));
}

__device__ __forceinline__ void ldsm4(uint32_t& a, uint32_t& b, uint32_t& c,
                                      uint32_t& d, uint32_t addr) {
    asm volatile(
        "ldmatrix.sync.aligned.m8n8.x4.shared.b16 {%0,%1,%2,%3}, [%4];"
        : "=r"(a), "=r"(b), "=r"(c), "=r"(d) : "r"(addr));
}

__device__ __forceinline__ uint32_t pack_h2(float x, float y) {
    __half2 h = __floats2half2_rn(x, y);
    return *reinterpret_cast<uint32_t*>(&h);
}

// 8 mask bits (pair s at bits 2s,2s+1) -> 4 half2 AND-words
__device__ __forceinline__ void expand4(uint32_t byte, uint32_t w[4]) {
    uint32_t lo = ((byte & 0xFu) * 0x00204081u) & 0x01010101u;
    uint32_t hi = (((byte >> 4) & 0xFu) * 0x00204081u) & 0x01010101u;
    lo *= 0xFFu;
    hi *= 0xFFu;
    w[0] = __byte_perm(lo, lo, 0x1100);
    w[1] = __byte_perm(lo, lo, 0x3322);
    w[2] = __byte_perm(hi, hi, 0x1100);
    w[3] = __byte_perm(hi, hi, 0x3322);
}

__device__ __forceinline__ void cp16(void* dst, const void* src) {
    uint32_t d = (uint32_t)__cvta_generic_to_shared(dst);
    asm volatile("cp.async.cg.shared.global [%0], [%1], 16;" :: "r"(d), "l"(src));
}
__device__ __forceinline__ void cp4(void* dst, const void* src) {
    uint32_t d = (uint32_t)__cvta_generic_to_shared(dst);
    asm volatile("cp.async.ca.shared.global [%0], [%1], 4;" :: "r"(d), "l"(src));
}
#define CP_COMMIT() asm volatile("cp.async.commit_group;")
#define CP_WAIT0()  asm volatile("cp.async.wait_group 0;")

// ============ fused preprocessing ============
__global__ void prep_all(const float* __restrict__ k, const float* __restrict__ v,
                         const int* __restrict__ m)
{
    __shared__ float st[64][33];
    const int bid = blockIdx.x;
    const int tid = threadIdx.x;

    if (bid < PREP_KBLK) {
        int idx = bid * 256 + tid;   // float4 index
        float4 t = reinterpret_cast<const float4*>(k)[idx];
        uint32_t h0 = pack_h2(t.x * SCALE_LOG2, t.y * SCALE_LOG2);
        uint32_t h1 = pack_h2(t.z * SCALE_LOG2, t.w * SCALE_LOG2);
        reinterpret_cast<uint2*>(g_kh)[idx] = make_uint2(h0, h1);
    } else if (bid < PREP_KBLK + PREP_VBLK) {
        const int vb = bid - PREP_KBLK;
        const int bh = vb >> 5, j0 = (vb & 31) * 64;
        const float* vbp = v + (long)bh * Ldim * Edim + (long)j0 * Edim;
        #pragma unroll
        for (int it = 0; it < 8; ++it) {
            int item = tid + 256 * it;
            int key = item >> 5, e = item & 31;
            st[key][e] = vbp[key * Edim + e];
        }
        __syncthreads();
        __half* oh = g_vt + (long)bh * Edim * Ldim + j0;
        #pragma unroll
        for (int it = 0; it < 8; ++it) {
            int item = tid + 256 * it;
            int e = item >> 6, key = item & 63;
            oh[(long)e * Ldim + key] = __float2half_rn(st[key][e]);
        }
    } else {
        const int row = bid - (PREP_KBLK + PREP_VBLK);   // b*L + i
        const int j8 = tid >> 3, t = (tid >> 1) & 3, ab = tid & 1;
        const int* mr = m + (long)row * Ldim + j8 * 64 + 2 * t + 8 * ab;
        uint32_t byte = 0;
        #pragma unroll
        for (int s = 0; s < 4; ++s) {
            int2 mm = *(const int2*)(mr + 16 * s);
            byte |= (mm.x != 0 ? 1u : 0u) << (2 * s);
            byte |= (mm.y != 0 ? 1u : 0u) << (2 * s + 1);
        }
        g_mpack[((long)row * 32 + j8) * 8 + t * 2 + ab] = (uint8_t)byte;
    }
}

// ============ attention ============

__global__ __launch_bounds__(128, 4)
void attn_kernel(const float* __restrict__ gq, float* __restrict__ gout)
{
    __shared__ __align__(16) __half kh_s[2][TK * KST];
    __shared__ __align__(16) __half v_s[2][VROWS * VST];
    __shared__ __align__(8) uint8_t m_s[2][TQ * 8];

    const int tid = threadIdx.x;
    const int w = tid >> 5, lane = tid & 31;
    const int g = lane >> 2, t = lane & 3;

    const int qt = blockIdx.x, h = blockIdx.y, b = blockIdx.z;
    const int i0 = qt * TQ;

    const long bh = (long)(b * Hdim + h) * Ldim * Edim;
    const float* qb = gq + bh + (long)i0 * Edim;
    const __half* KHg = g_kh + bh;
    const __half* Vg = g_vt + bh;          // [e][key]
    const uint8_t* MBg = g_mpack + ((long)(b * Ldim + i0)) * 32 * 8;

    // ---- Q fragments (persistent, single fp16; scale folded into K) ----
    const int r0 = w * 16 + g;
    uint32_t Q0[4], Q1[4];
    {
        const float* q0 = qb + (long)r0 * Edim;
        const float* q1 = qb + (long)(r0 + 8) * Edim;
        #pragma unroll
        for (int ks = 0; ks < 2; ++ks) {
            uint32_t* Qf = ks ? Q1 : Q0;
            float2 x0 = *(const float2*)(q0 + 2 * t + 16 * ks);
            float2 x1 = *(const float2*)(q1 + 2 * t + 16 * ks);
            float2 x2 = *(const float2*)(q0 + 2 * t + 8 + 16 * ks);
            float2 x3 = *(const float2*)(q1 + 2 * t + 8 + 16 * ks);
            Qf[0] = pack_h2(x0.x, x0.y);
            Qf[1] = pack_h2(x1.x, x1.y);
            Qf[2] = pack_h2(x2.x, x2.y);
            Qf[3] = pack_h2(x3.x, x3.y);
        }
    }

    // ldmatrix base addresses (per stage)
    uint32_t kbase[2], vbase[2];
    {
        uint32_t koff = ((lane & 7) * KST + (lane >> 3) * 8) * 2;
        uint32_t voff = ((lane & 7) * VST + (lane >> 3) * 8) * 2;
        kbase[0] = (uint32_t)__cvta_generic_to_shared(&kh_s[0][0]) + koff;
        kbase[1] = (uint32_t)__cvta_generic_to_shared(&kh_s[1][0]) + koff;
        vbase[0] = (uint32_t)__cvta_generic_to_shared(&v_s[0][0]) + voff;
        vbase[1] = (uint32_t)__cvta_generic_to_shared(&v_s[1][0]) + voff;
    }

    // O[0..3] = P*V output columns; l accumulated in fp32 registers
    float O[4][4];
    #pragma unroll
    for (int n = 0; n < 4; ++n)
        #pragma unroll
        for (int j = 0; j < 4; ++j) O[n][j] = 0.0f;
    float l0 = 0.0f, l1 = 0.0f;

    auto load_tile = [&](int st, int jt) {
        const int j0 = jt * TK;
        #pragma unroll
        for (int it = 0; it < 2; ++it) {
            int item = tid + 128 * it;
            int key = item >> 2, seg = item & 3;
            cp16(&kh_s[st][key * KST + seg * 8],
                 KHg + (long)(j0 + key) * Edim + seg * 8);
        }
        #pragma unroll
        for (int it = 0; it < 2; ++it) {
            int item = tid + 128 * it;
            int e = item >> 3, seg = item & 7;
            cp16(&v_s[st][e * VST + seg * 8], Vg + (long)e * Ldim + j0 + seg * 8);
        }
        {
            int row = tid >> 1, half = tid & 1;
            cp4(&m_s[st][row * 8 + half * 4],
                MBg + (long)row * 32 * 8 + jt * 8 + half * 4);
        }
    };

    load_tile(0, 0);
    CP_COMMIT();

    #pragma unroll 2
    for (int jt = 0; jt < NT; ++jt) {
        CP_WAIT0();
        __syncthreads();
        if (jt + 1 < NT) { load_tile((jt + 1) & 1, jt + 1); CP_COMMIT(); }

        const int st = jt & 1;

        // ---- prefetch mask rows (LDS latency overlaps GEMM1) ----
        const uint16_t mr0 = *(const uint16_t*)&m_s[st][r0 * 8 + 2 * t];
        const uint16_t mr1 = *(const uint16_t*)&m_s[st][(r0 + 8) * 8 + 2 * t];

        // ---- GEMM1: S(16x64) = Q*K, one independent HMMA stream ----
        float S[8][4];
        #pragma unroll
        for (int n = 0; n < 8; ++n)
            #pragma unroll
            for (int j = 0; j < 4; ++j) S[n][j] = 0.0f;

        #pragma unroll
        for (int n = 0; n < 8; ++n) {
            uint32_t b0, b1, b2, b3;
            ldsm4(b0, b1, b2, b3, kbase[st] + n * (8 * KST * 2));
            mma_f16(S[n], Q0, b0, b1);
            mma_f16(S[n], Q1, b2, b3);
        }

        // ---- mask AND-words ----
        uint32_t wA0[4], wB0[4], wA1[4], wB1[4];
        expand4(mr0 & 0xFFu, wA0);
        expand4(mr0 >> 8, wB0);
        expand4(mr1 & 0xFFu, wA1);
        expand4(mr1 >> 8, wB1);

        // ==== phase A: softmax chunks 0-1 (f16x2 ex2), l-tree, GEMM2 half 0 ====
        uint32_t Ap[4][4];
        #pragma unroll
        for (int s = 0; s < 2; ++s) {
            Ap[s][0] = h2ex2(pack_h2(S[2 * s][0], S[2 * s][1])) & wA0[s];
            Ap[s][1] = h2ex2(pack_h2(S[2 * s][2], S[2 * s][3])) & wA1[s];
            Ap[s][2] = h2ex2(pack_h2(S[2 * s + 1][0], S[2 * s + 1][1])) & wB0[s];
            Ap[s][3] = h2ex2(pack_h2(S[2 * s + 1][2], S[2 * s + 1][3])) & wB1[s];
        }
        {
            __half2 a0 = __hadd2(*(__half2*)&Ap[0][0], *(__half2*)&Ap[0][2]);
            __half2 a1 = __hadd2(*(__half2*)&Ap[1][0], *(__half2*)&Ap[1][2]);
            __half2 b0 = __hadd2(*(__half2*)&Ap[0][1], *(__half2*)&Ap[0][3]);
            __half2 b1 = __hadd2(*(__half2*)&Ap[1][1], *(__half2*)&Ap[1][3]);
            float2 fa = __half22float2(__hadd2(a0, a1));
            float2 fb = __half22float2(__hadd2(b0, b1));
            l0 += fa.x + fa.y;
            l1 += fb.x + fb.y;
        }
        #pragma unroll
        for (int n = 0; n < 4; ++n) {
            uint32_t c0, c1, c2, c3;
            ldsm4(c0, c1, c2, c3, vbase[st] + n * (8 * VST * 2));
            mma_f16(O[n], Ap[0], c0, c1);
            mma_f16(O[n], Ap[1], c2, c3);
        }

        // ==== phase B: softmax chunks 2-3 (f16x2 ex2), l-tree, GEMM2 half 1 ====
        #pragma unroll
        for (int s = 2; s < 4; ++s) {
            Ap[s][0] = h2ex2(pack_h2(S[2 * s][0], S[2 * s][1])) & wA0[s];
            Ap[s][1] = h2ex2(pack_h2(S[2 * s][2], S[2 * s][3])) & wA1[s];
            Ap[s][2] = h2ex2(pack_h2(S[2 * s + 1][0], S[2 * s + 1][1])) & wB0[s];
            Ap[s][3] = h2ex2(pack_h2(S[2 * s + 1][2], S[2 * s + 1][3])) & wB1[s];
        }
        {
            __half2 a0 = __hadd2(*(__half2*)&Ap[2][0], *(__half2*)&Ap[2][2]);
            __half2 a1 = __hadd2(*(__half2*)&Ap[3][0], *(__half2*)&Ap[3][2]);
            __half2 b0 = __hadd2(*(__half2*)&Ap[2][1], *(__half2*)&Ap[2][3]);
            __half2 b1 = __hadd2(*(__half2*)&Ap[3][1], *(__half2*)&Ap[3][3]);
            float2 fa = __half22float2(__hadd2(a0, a1));
            float2 fb = __half22float2(__hadd2(b0, b1));
            l0 += fa.x + fa.y;
            l1 += fb.x + fb.y;
        }
        #pragma unroll
        for (int n = 0; n < 4; ++n) {
            uint32_t c0, c1, c2, c3;
            ldsm4(c0, c1, c2, c3, vbase[st] + n * (8 * VST * 2) + 64);
            mma_f16(O[n], Ap[2], c0, c1);
            mma_f16(O[n], Ap[3], c2, c3);
        }
    }

    // ---- finalize: reduce l across the 4 t-lanes of the quad ----
    l0 += __shfl_xor_sync(0xffffffffu, l0, 1);
    l0 += __shfl_xor_sync(0xffffffffu, l0, 2);
    l1 += __shfl_xor_sync(0xffffffffu, l1, 1);
    l1 += __shfl_xor_sync(0xffffffffu, l1, 2);
    const float inv0 = (l0 > 0.0f) ? (1.0f / l0) : 0.0f;
    const float inv1 = (l1 > 0.0f) ? (1.0f / l1) : 0.0f;

    float* ob0 = gout + bh + (long)(i0 + r0) * Edim;
    float* ob1 = gout + bh + (long)(i0 + r0 + 8) * Edim;
    #pragma unroll
    for (int n = 0; n < 4; ++n) {
        float2 o0 = make_float2(O[n][0] * inv0, O[n][1] * inv0);
        float2 o1 = make_float2(O[n][2] * inv1, O[n][3] * inv1);
        *(float2*)(ob0 + 8 * n + 2 * t) = o0;
        *(float2*)(ob1 + 8 * n + 2 * t) = o1;
    }
}

extern "C" void kernel_launch(void* const* d_in, const int* in_sizes, int n_in,
                              void* d_out, int out_size)
{
    const float* q = (const float*)d_in[0];
    const float* k = (const float*)d_in[1];
    const float* v = (const float*)d_in[2];
    const int*   m = (const int*)d_in[3];
    float* out = (float*)d_out;

    prep_all<<<PREP_KBLK + PREP_VBLK + PREP_MBLK, 256>>>(k, v, m);

    dim3 grid(Ldim / TQ, Hdim, Bdim);
    attn_kernel<<<grid, 128>>>(q, out);
}